// round 10
// baseline (speedup 1.0000x reference)
#include <cuda_runtime.h>
#include <cuda_bf16.h>
#include <cstdint>

#define BATCH 2
#define SEQ   2048
#define SA    2051
#define HID   1024
#define NH    16
#define HD    64
#define SEQSTR ((size_t)BATCH * SA * HID)
#define MROWS  (2 * BATCH * SA)          // 8204 rows (both seqs)

// ---------------- scratch ----------------------------------------------------
__device__ float g_aug [2 * BATCH * SA * HID];
__device__ float g_q   [2 * BATCH * NH * SA * HD];
__device__ float g_k   [2 * BATCH * NH * SA * HD];
__device__ float g_v   [2 * BATCH * NH * SA * HD];
__device__ float g_att [2 * BATCH * SA * HID];
__device__ float g_proj[2 * BATCH * SA * HID];

// ---------------- helpers ----------------------------------------------------
__device__ __forceinline__ uint32_t f2tf(float x) {
    uint32_t r;
    asm("cvt.rna.tf32.f32 %0, %1;" : "=r"(r) : "f"(x));
    return r;
}

__device__ __forceinline__ void mma_tf32(float* c, const uint32_t* a, const uint32_t* b) {
    asm volatile(
        "mma.sync.aligned.m16n8k8.row.col.f32.tf32.tf32.f32 "
        "{%0,%1,%2,%3}, {%4,%5,%6,%7}, {%8,%9}, {%0,%1,%2,%3};"
        : "+f"(c[0]), "+f"(c[1]), "+f"(c[2]), "+f"(c[3])
        : "r"(a[0]), "r"(a[1]), "r"(a[2]), "r"(a[3]), "r"(b[0]), "r"(b[1]));
}

// ---------------- build augmented sequences ----------------------------------
__global__ void build_aug_kernel(const float* __restrict__ cnn,
                                 const float* __restrict__ llm,
                                 const float* __restrict__ ee,
                                 const float* __restrict__ me,
                                 const float* __restrict__ pe,
                                 float* __restrict__ aug)
{
    int s = blockIdx.x, b = blockIdx.y, seq = blockIdx.z;
    const float* src;
    if (s < SEQ) src = (seq == 0 ? cnn : llm) + ((size_t)b * SEQ + s) * HID;
    else         src = (s == SEQ ? ee : (s == SEQ + 1 ? me : pe));
    float* dst = aug + (((size_t)seq * BATCH + b) * SA + s) * HID;
    int j = threadIdx.x * 4;
    float4 v = *(const float4*)(src + j);
    *(float4*)(dst + j) = v;
}

// ---------------- TF32 GEMM, warp tile 64x64, fused over z -------------------
// X [M,1024] row-major; W [1024,1024] row-major ([in][out]).
// CTA tile 128x128, 4 warps (2m x 2n of 64x64), BK=16, double-buffered.
// blockIdx.z selects (W, bias, Y) triple.
template<int OUT_HEADMAJOR>
__global__ __launch_bounds__(128, 2) void gemm_tc(
    const float* __restrict__ X,
    const float* __restrict__ W0, const float* __restrict__ W1, const float* __restrict__ W2,
    const float* __restrict__ bias0, const float* __restrict__ bias1, const float* __restrict__ bias2,
    float* __restrict__ Y0, float* __restrict__ Y1, float* __restrict__ Y2,
    int M)
{
    __shared__ uint32_t As[2][16][136];   // [k][m], pad 136 (== 8 mod 32)
    __shared__ uint32_t Bs[2][16][136];   // [k][n]
    const int K = 1024;

    int z = blockIdx.z;
    const float* W    = (z == 0) ? W0 : (z == 1) ? W1 : W2;
    const float* bias = (z == 0) ? bias0 : (z == 1) ? bias1 : bias2;
    float*       Y    = (z == 0) ? Y0 : (z == 1) ? Y1 : Y2;

    int m0 = blockIdx.x * 128, n0 = blockIdx.y * 128;
    int tid = threadIdx.x, lane = tid & 31, warp = tid >> 5;
    int wm = warp & 1, wn = warp >> 1;
    int g = lane >> 2, t = lane & 3;

    float acc[4][8][4];
#pragma unroll
    for (int mt = 0; mt < 4; mt++)
#pragma unroll
        for (int j = 0; j < 8; j++)
#pragma unroll
            for (int c = 0; c < 4; c++) acc[mt][j][c] = 0.f;

    // A loader: thread owns row m0+tid, 16 k-values (4 float4)
    int arow = m0 + tid;
    bool aval = arow < M;
    const float* Xrow = X + (size_t)arow * K;
    // B loader: thread owns k-row tid>>3, 16 n-values
    int brow = tid >> 3, bcol = (tid & 7) * 16;

    float4 av[4], bv[4];
    const float4 z4 = make_float4(0.f, 0.f, 0.f, 0.f);

    // prologue (k0 = 0)
#pragma unroll
    for (int u = 0; u < 4; u++) {
        av[u] = aval ? *(const float4*)(Xrow + u * 4) : z4;
        bv[u] = *(const float4*)(W + (size_t)brow * HID + n0 + bcol + u * 4);
    }
#pragma unroll
    for (int u = 0; u < 4; u++) {
        As[0][u * 4 + 0][tid] = f2tf(av[u].x);
        As[0][u * 4 + 1][tid] = f2tf(av[u].y);
        As[0][u * 4 + 2][tid] = f2tf(av[u].z);
        As[0][u * 4 + 3][tid] = f2tf(av[u].w);
        uint4 p = make_uint4(f2tf(bv[u].x), f2tf(bv[u].y), f2tf(bv[u].z), f2tf(bv[u].w));
        *(uint4*)(&Bs[0][brow][bcol + u * 4]) = p;
    }
    __syncthreads();

    int cur = 0;
    for (int k0 = 0; k0 < K; k0 += 16) {
        int nk = k0 + 16;
        if (nk < K) {
#pragma unroll
            for (int u = 0; u < 4; u++) {
                av[u] = aval ? *(const float4*)(Xrow + nk + u * 4) : z4;
                bv[u] = *(const float4*)(W + (size_t)(nk + brow) * HID + n0 + bcol + u * 4);
            }
        }
#pragma unroll
        for (int ks = 0; ks < 2; ks++) {
            int kb = ks * 8;
            uint32_t af[4][4], bf[8][2];
#pragma unroll
            for (int mt = 0; mt < 4; mt++) {
                int m = wm * 64 + mt * 16 + g;
                af[mt][0] = As[cur][kb + t][m];
                af[mt][1] = As[cur][kb + t][m + 8];
                af[mt][2] = As[cur][kb + t + 4][m];
                af[mt][3] = As[cur][kb + t + 4][m + 8];
            }
#pragma unroll
            for (int j = 0; j < 8; j++) {
                int n = wn * 64 + j * 8 + g;
                bf[j][0] = Bs[cur][kb + t][n];
                bf[j][1] = Bs[cur][kb + t + 4][n];
            }
#pragma unroll
            for (int mt = 0; mt < 4; mt++)
#pragma unroll
                for (int j = 0; j < 8; j++)
                    mma_tf32(acc[mt][j], af[mt], bf[j]);
        }
        if (nk < K) {
            int nb = cur ^ 1;
#pragma unroll
            for (int u = 0; u < 4; u++) {
                As[nb][u * 4 + 0][tid] = f2tf(av[u].x);
                As[nb][u * 4 + 1][tid] = f2tf(av[u].y);
                As[nb][u * 4 + 2][tid] = f2tf(av[u].z);
                As[nb][u * 4 + 3][tid] = f2tf(av[u].w);
                uint4 p = make_uint4(f2tf(bv[u].x), f2tf(bv[u].y), f2tf(bv[u].z), f2tf(bv[u].w));
                *(uint4*)(&Bs[nb][brow][bcol + u * 4]) = p;
            }
            __syncthreads();
            cur = nb;
        }
    }

    // epilogue
#pragma unroll
    for (int mt = 0; mt < 4; mt++) {
#pragma unroll
        for (int rr = 0; rr < 2; rr++) {
            int gm = m0 + wm * 64 + mt * 16 + g + rr * 8;
            if (gm >= M) continue;
            int seq = 0, b = 0, s = 0;
            if (OUT_HEADMAJOR) {
                seq = gm / (BATCH * SA);
                int r = gm - seq * (BATCH * SA);
                b = r / SA;
                s = r - b * SA;
            }
#pragma unroll
            for (int j = 0; j < 8; j++) {
                int n = n0 + wn * 64 + j * 8 + t * 2;
                float2 o = make_float2(acc[mt][j][rr * 2] + bias[n],
                                       acc[mt][j][rr * 2 + 1] + bias[n + 1]);
                if (OUT_HEADMAJOR) {
                    int h = n >> 6, d = n & 63;
                    *(float2*)(Y + (size_t)seq * SEQSTR +
                               (((size_t)b * NH + h) * SA + s) * HD + d) = o;
                } else {
                    *(float2*)(Y + (size_t)gm * HID + n) = o;
                }
            }
        }
    }
}

// ---------------- TF32 flash attention, BQ=128, both dirs fused --------------
// q/k/v: [dir][B, NH, SA, HD]; out: [dir][B, SA, HID]
// Physics biases are per-row softmax-invariant constants -> dropped.
// blockIdx.z: bit0 = b, bit1 = dir. 256 threads = 8 warps, 16 q-rows/warp.
__global__ __launch_bounds__(256) void attn_tf32(
    const float* __restrict__ qall, const float* __restrict__ kall,
    const float* __restrict__ vall, float* __restrict__ attall)
{
    __shared__ uint32_t Ks[64][68];   // pad 68 (== 4 mod 32)
    __shared__ uint32_t Vs[64][72];   // pad 72 (== 8 mod 32)

    int qt = blockIdx.x, h = blockIdx.y;
    int b = blockIdx.z & 1, dir = blockIdx.z >> 1;
    const float* Q  = qall + (size_t)dir * SEQSTR;
    const float* Kx = kall + (size_t)(dir ^ 1) * SEQSTR;
    const float* V  = vall + (size_t)(dir ^ 1) * SEQSTR;
    float* attout   = attall + (size_t)dir * SEQSTR;

    int tid = threadIdx.x;
    int lane = tid & 31, warp = tid >> 5;
    int g = lane >> 2, t = lane & 3;
    const size_t hoff = ((size_t)b * NH + h) * (size_t)SA * HD;
    int q0 = qt * 128;

    // ---- stage Q (scaled by 1/8) in two 64-row passes through Ks ----
    uint32_t qf[8][4];
#pragma unroll
    for (int half = 0; half < 2; half++) {
        for (int i = tid; i < 64 * 16; i += 256) {
            int r = i >> 4, c = (i & 15) * 4;
            int gq = q0 + half * 64 + r;
            float4 v = make_float4(0.f, 0.f, 0.f, 0.f);
            if (gq < SA) v = *(const float4*)(Q + hoff + (size_t)gq * HD + c);
            Ks[r][c + 0] = f2tf(v.x * 0.125f); Ks[r][c + 1] = f2tf(v.y * 0.125f);
            Ks[r][c + 2] = f2tf(v.z * 0.125f); Ks[r][c + 3] = f2tf(v.w * 0.125f);
        }
        __syncthreads();
        if ((warp >> 2) == half) {
            int m = (warp & 3) * 16;
#pragma unroll
            for (int kc = 0; kc < 8; kc++) {
                qf[kc][0] = Ks[m + g][kc * 8 + t];
                qf[kc][1] = Ks[m + 8 + g][kc * 8 + t];
                qf[kc][2] = Ks[m + g][kc * 8 + t + 4];
                qf[kc][3] = Ks[m + 8 + g][kc * 8 + t + 4];
            }
        }
        __syncthreads();
    }

    float o[8][4];
#pragma unroll
    for (int nd = 0; nd < 8; nd++)
#pragma unroll
        for (int c = 0; c < 4; c++) o[nd][c] = 0.f;
    float mrow0 = -1e30f, mrow1 = -1e30f, lrow0 = 0.f, lrow1 = 0.f;

    for (int k0 = 0; k0 < SA; k0 += 64) {
        __syncthreads();
        for (int i = tid; i < 64 * 16; i += 256) {
            int r = i >> 4, c = (i & 15) * 4;
            int gk = k0 + r;
            float4 kv = make_float4(0.f, 0.f, 0.f, 0.f), vv = kv;
            if (gk < SA) {
                kv = *(const float4*)(Kx + hoff + (size_t)gk * HD + c);
                vv = *(const float4*)(V  + hoff + (size_t)gk * HD + c);
            }
            Ks[r][c + 0] = f2tf(kv.x); Ks[r][c + 1] = f2tf(kv.y);
            Ks[r][c + 2] = f2tf(kv.z); Ks[r][c + 3] = f2tf(kv.w);
            Vs[r][c + 0] = f2tf(vv.x); Vs[r][c + 1] = f2tf(vv.y);
            Vs[r][c + 2] = f2tf(vv.z); Vs[r][c + 3] = f2tf(vv.w);
        }
        __syncthreads();

        // ---- S = (Q/8) @ K^T ----
        float s[8][4];
#pragma unroll
        for (int j = 0; j < 8; j++)
#pragma unroll
            for (int c = 0; c < 4; c++) s[j][c] = 0.f;
#pragma unroll
        for (int j = 0; j < 8; j++) {
#pragma unroll
            for (int kc = 0; kc < 8; kc++) {
                uint32_t bf[2];
                bf[0] = Ks[j * 8 + g][kc * 8 + t];
                bf[1] = Ks[j * 8 + g][kc * 8 + t + 4];
                mma_tf32(s[j], qf[kc], bf);
            }
        }

        // ---- mask invalid keys ----
        int kvalid = SA - k0;
        if (kvalid < 64) {
#pragma unroll
            for (int j = 0; j < 8; j++) {
                int c0 = j * 8 + t * 2, c1 = c0 + 1;
                if (c0 >= kvalid) { s[j][0] = -1e30f; s[j][2] = -1e30f; }
                if (c1 >= kvalid) { s[j][1] = -1e30f; s[j][3] = -1e30f; }
            }
        }

        // ---- online softmax (rows g, g+8 spread over 4 lanes) ----
        float tm0 = -1e30f, tm1 = -1e30f;
#pragma unroll
        for (int j = 0; j < 8; j++) {
            tm0 = fmaxf(tm0, fmaxf(s[j][0], s[j][1]));
            tm1 = fmaxf(tm1, fmaxf(s[j][2], s[j][3]));
        }
        tm0 = fmaxf(tm0, __shfl_xor_sync(0xffffffffu, tm0, 1));
        tm0 = fmaxf(tm0, __shfl_xor_sync(0xffffffffu, tm0, 2));
        tm1 = fmaxf(tm1, __shfl_xor_sync(0xffffffffu, tm1, 1));
        tm1 = fmaxf(tm1, __shfl_xor_sync(0xffffffffu, tm1, 2));
        float nm0 = fmaxf(mrow0, tm0), nm1 = fmaxf(mrow1, tm1);
        float corr0 = __expf(mrow0 - nm0), corr1 = __expf(mrow1 - nm1);
        float sum0 = 0.f, sum1 = 0.f;
#pragma unroll
        for (int j = 0; j < 8; j++) {
            s[j][0] = __expf(s[j][0] - nm0);
            s[j][1] = __expf(s[j][1] - nm0);
            s[j][2] = __expf(s[j][2] - nm1);
            s[j][3] = __expf(s[j][3] - nm1);
            sum0 += s[j][0] + s[j][1];
            sum1 += s[j][2] + s[j][3];
        }
        sum0 += __shfl_xor_sync(0xffffffffu, sum0, 1);
        sum0 += __shfl_xor_sync(0xffffffffu, sum0, 2);
        sum1 += __shfl_xor_sync(0xffffffffu, sum1, 1);
        sum1 += __shfl_xor_sync(0xffffffffu, sum1, 2);
        lrow0 = lrow0 * corr0 + sum0;  mrow0 = nm0;
        lrow1 = lrow1 * corr1 + sum1;  mrow1 = nm1;
#pragma unroll
        for (int nd = 0; nd < 8; nd++) {
            o[nd][0] *= corr0; o[nd][1] *= corr0;
            o[nd][2] *= corr1; o[nd][3] *= corr1;
        }

        // ---- O += P @ V (P -> A-fragments via shuffles) ----
        int s0l = (lane & 28) + (t >> 1);
#pragma unroll
        for (int j = 0; j < 8; j++) {
            float e0 = __shfl_sync(0xffffffffu, s[j][0], s0l);
            float e1 = __shfl_sync(0xffffffffu, s[j][1], s0l);
            float f0 = __shfl_sync(0xffffffffu, s[j][2], s0l);
            float f1 = __shfl_sync(0xffffffffu, s[j][3], s0l);
            float e2 = __shfl_sync(0xffffffffu, s[j][0], s0l + 2);
            float e3 = __shfl_sync(0xffffffffu, s[j][1], s0l + 2);
            float f2 = __shfl_sync(0xffffffffu, s[j][2], s0l + 2);
            float f3 = __shfl_sync(0xffffffffu, s[j][3], s0l + 2);
            uint32_t af[4];
            af[0] = f2tf((t & 1) ? e1 : e0);
            af[1] = f2tf((t & 1) ? f1 : f0);
            af[2] = f2tf((t & 1) ? e3 : e2);
            af[3] = f2tf((t & 1) ? f3 : f2);
#pragma unroll
            for (int nd = 0; nd < 8; nd++) {
                uint32_t bf[2];
                bf[0] = Vs[j * 8 + t][nd * 8 + g];
                bf[1] = Vs[j * 8 + t + 4][nd * 8 + g];
                mma_tf32(o[nd], af, bf);
            }
        }
    }

    // ---- write attended rows ----
    float inv0 = 1.0f / lrow0, inv1 = 1.0f / lrow1;
    int row0 = q0 + warp * 16 + g, row1 = row0 + 8;
    int cb = h * HD;
#pragma unroll
    for (int nd = 0; nd < 8; nd++) {
        int col = cb + nd * 8 + t * 2;
        if (row0 < SA) {
            float2 v = make_float2(o[nd][0] * inv0, o[nd][1] * inv0);
            *(float2*)(attout + ((size_t)b * SA + row0) * HID + col) = v;
        }
        if (row1 < SA) {
            float2 v = make_float2(o[nd][2] * inv1, o[nd][3] * inv1);
            *(float2*)(attout + ((size_t)b * SA + row1) * HID + col) = v;
        }
    }
}

// ---------------- residual + LayerNorm epilogue ------------------------------
__global__ __launch_bounds__(256) void ln_kernel(
    const float* __restrict__ aug, const float* __restrict__ proj,
    const float* __restrict__ gamma, const float* __restrict__ beta,
    float* __restrict__ out)
{
    int s = blockIdx.x, b = blockIdx.y, seq = blockIdx.z;
    int tid = threadIdx.x;
    size_t roff = (((size_t)seq * BATCH + b) * SA + s) * HID;
    int j = tid * 4;

    float4 a = *(const float4*)(aug + roff + j);
    float4 p = *(const float4*)(proj + roff + j);
    float4 x = make_float4(a.x + p.x, a.y + p.y, a.z + p.z, a.w + p.w);

    __shared__ float wsum[8];
    float lsum = x.x + x.y + x.z + x.w;
#pragma unroll
    for (int m = 16; m >= 1; m >>= 1) lsum += __shfl_xor_sync(0xffffffffu, lsum, m);
    if ((tid & 31) == 0) wsum[tid >> 5] = lsum;
    __syncthreads();
    float tot = 0.f;
#pragma unroll
    for (int w = 0; w < 8; w++) tot += wsum[w];
    float mean = tot * (1.0f / HID);

    float dx = x.x - mean, dy = x.y - mean, dz = x.z - mean, dw = x.w - mean;
    float lvar = dx * dx + dy * dy + dz * dz + dw * dw;
#pragma unroll
    for (int m = 16; m >= 1; m >>= 1) lvar += __shfl_xor_sync(0xffffffffu, lvar, m);
    __syncthreads();
    if ((tid & 31) == 0) wsum[tid >> 5] = lvar;
    __syncthreads();
    float tot2 = 0.f;
#pragma unroll
    for (int w = 0; w < 8; w++) tot2 += wsum[w];
    float rstd = rsqrtf(tot2 * (1.0f / HID) + 1e-5f);

    float4 g = *(const float4*)(gamma + j);
    float4 be = *(const float4*)(beta + j);
    float4 oo = make_float4(dx * rstd * g.x + be.x, dy * rstd * g.y + be.y,
                            dz * rstd * g.z + be.z, dw * rstd * g.w + be.w);
    size_t oidx = (size_t)seq * (2ull * SEQ * HID) + ((size_t)b * SEQ + s) * HID + j;
    *(float4*)(out + oidx) = oo;
}

// ---------------- launch ------------------------------------------------------
extern "C" void kernel_launch(void* const* d_in, const int* in_sizes, int n_in,
                              void* d_out, int out_size)
{
    const float* cnn = (const float*)d_in[0];
    const float* llm = (const float*)d_in[1];
    const float* Wq  = (const float*)d_in[2];  const float* bq = (const float*)d_in[3];
    const float* Wk  = (const float*)d_in[4];  const float* bk = (const float*)d_in[5];
    const float* Wv  = (const float*)d_in[6];  const float* bv = (const float*)d_in[7];
    const float* Wo  = (const float*)d_in[8];  const float* bo = (const float*)d_in[9];
    const float* ee  = (const float*)d_in[10];
    const float* me  = (const float*)d_in[11];
    const float* pe  = (const float*)d_in[12];
    const float* gamma = (const float*)d_in[13];
    const float* beta  = (const float*)d_in[14];

    float *aug, *q, *k, *v, *att, *proj;
    cudaGetSymbolAddress((void**)&aug,  g_aug);
    cudaGetSymbolAddress((void**)&q,    g_q);
    cudaGetSymbolAddress((void**)&k,    g_k);
    cudaGetSymbolAddress((void**)&v,    g_v);
    cudaGetSymbolAddress((void**)&att,  g_att);
    cudaGetSymbolAddress((void**)&proj, g_proj);

    build_aug_kernel<<<dim3(SA, BATCH, 2), 256>>>(cnn, llm, ee, me, pe, aug);

    const int M = MROWS;                              // 8204
    dim3 gqkv((M + 127) / 128, HID / 128, 3);         // (65, 8, 3)
    gemm_tc<1><<<gqkv, 128>>>(aug, Wq, Wk, Wv, bq, bk, bv, q, k, v, M);

    dim3 ga((SA + 127) / 128, NH, 4);                 // (17, 16, 4)
    attn_tf32<<<ga, 256>>>(q, k, v, att);

    dim3 go((M + 127) / 128, HID / 128, 1);           // (65, 8)
    gemm_tc<0><<<go, 128>>>(att, Wo, Wo, Wo, bo, bo, bo, proj, proj, proj, M);

    ln_kernel<<<dim3(SEQ, BATCH, 2), 256>>>(aug, proj, gamma, beta, (float*)d_out);
}

// round 13
// speedup vs baseline: 1.1477x; 1.1477x over previous
#include <cuda_runtime.h>
#include <cuda_bf16.h>
#include <cstdint>

#define BATCH 2
#define SEQ   2048
#define SA    2051
#define HID   1024
#define NH    16
#define HD    64
#define SEQSTR ((size_t)BATCH * SA * HID)
#define MROWS  (2 * BATCH * SA)          // 8204 rows (both seqs)

// ---------------- scratch ----------------------------------------------------
__device__ float g_aug [2 * BATCH * SA * HID];
__device__ float g_q   [2 * BATCH * NH * SA * HD];
__device__ float g_k   [2 * BATCH * NH * SA * HD];
__device__ float g_v   [2 * BATCH * NH * SA * HD];
__device__ float g_att [2 * BATCH * SA * HID];
__device__ float g_proj[2 * BATCH * SA * HID];

// ---------------- helpers ----------------------------------------------------
__device__ __forceinline__ uint32_t f2tf(float x) {
    uint32_t r;
    asm("cvt.rna.tf32.f32 %0, %1;" : "=r"(r) : "f"(x));
    return r;
}

__device__ __forceinline__ void mma_tf32(float* c, const uint32_t* a, const uint32_t* b) {
    asm volatile(
        "mma.sync.aligned.m16n8k8.row.col.f32.tf32.tf32.f32 "
        "{%0,%1,%2,%3}, {%4,%5,%6,%7}, {%8,%9}, {%0,%1,%2,%3};"
        : "+f"(c[0]), "+f"(c[1]), "+f"(c[2]), "+f"(c[3])
        : "r"(a[0]), "r"(a[1]), "r"(a[2]), "r"(a[3]), "r"(b[0]), "r"(b[1]));
}

// ---------------- build augmented sequences ----------------------------------
__global__ void build_aug_kernel(const float* __restrict__ cnn,
                                 const float* __restrict__ llm,
                                 const float* __restrict__ ee,
                                 const float* __restrict__ me,
                                 const float* __restrict__ pe,
                                 float* __restrict__ aug)
{
    int s = blockIdx.x, b = blockIdx.y, seq = blockIdx.z;
    const float* src;
    if (s < SEQ) src = (seq == 0 ? cnn : llm) + ((size_t)b * SEQ + s) * HID;
    else         src = (s == SEQ ? ee : (s == SEQ + 1 ? me : pe));
    float* dst = aug + (((size_t)seq * BATCH + b) * SA + s) * HID;
    int j = threadIdx.x * 4;
    float4 v = *(const float4*)(src + j);
    *(float4*)(dst + j) = v;
}

// ---------------- TF32 tensor-core GEMM (R5 config + z-fusion) ---------------
// X [M,1024] row-major, W [1024,1024] row-major. BM=BN=128, BK=16, 256 thr.
// 8 warps: 4(m) x 2(n), warp tile 32x64. blockIdx.z selects (W,bias,Y).
template<int OUT_HEADMAJOR>
__global__ __launch_bounds__(256) void sgemm_tf32(
    const float* __restrict__ X,
    const float* __restrict__ W0, const float* __restrict__ W1, const float* __restrict__ W2,
    const float* __restrict__ bias0, const float* __restrict__ bias1, const float* __restrict__ bias2,
    float* __restrict__ Y0, float* __restrict__ Y1, float* __restrict__ Y2,
    int M)
{
    __shared__ uint32_t As[2][16][136];   // [k][m], pad 136 (=8 mod 32)
    __shared__ uint32_t Bs[2][16][136];   // [k][n]

    const int K = 1024;
    int z = blockIdx.z;
    const float* W    = (z == 0) ? W0 : (z == 1) ? W1 : W2;
    const float* bias = (z == 0) ? bias0 : (z == 1) ? bias1 : bias2;
    float*       Y    = (z == 0) ? Y0 : (z == 1) ? Y1 : Y2;

    int m0 = blockIdx.x * 128, n0 = blockIdx.y * 128;
    int tid = threadIdx.x;
    int lane = tid & 31, warp = tid >> 5;
    int wm = warp & 3, wn = warp >> 2;
    int g = lane >> 2, t = lane & 3;

    float acc[2][8][4];
#pragma unroll
    for (int mt = 0; mt < 2; mt++)
#pragma unroll
        for (int j = 0; j < 8; j++)
#pragma unroll
            for (int c = 0; c < 4; c++) acc[mt][j][c] = 0.f;

    // loader indices
    int ar = tid >> 2;            // 0..63 (and +64)
    int ac = (tid & 3) * 4;       // k offset within 16
    int br = tid >> 4;            // 0..15 (k)
    int bc = (tid & 15) * 8;      // n offset

    float4 av0, av1, bv0, bv1;
    const float4 z4 = make_float4(0.f, 0.f, 0.f, 0.f);

    // prologue load k0 = 0
    {
        int m1 = m0 + ar, m2 = m0 + ar + 64;
        av0 = (m1 < M) ? *(const float4*)(X + (size_t)m1 * K + ac) : z4;
        av1 = (m2 < M) ? *(const float4*)(X + (size_t)m2 * K + ac) : z4;
        bv0 = *(const float4*)(W + (size_t)br * HID + n0 + bc);
        bv1 = *(const float4*)(W + (size_t)br * HID + n0 + bc + 4);
        As[0][ac + 0][ar] = f2tf(av0.x); As[0][ac + 1][ar] = f2tf(av0.y);
        As[0][ac + 2][ar] = f2tf(av0.z); As[0][ac + 3][ar] = f2tf(av0.w);
        As[0][ac + 0][ar + 64] = f2tf(av1.x); As[0][ac + 1][ar + 64] = f2tf(av1.y);
        As[0][ac + 2][ar + 64] = f2tf(av1.z); As[0][ac + 3][ar + 64] = f2tf(av1.w);
        Bs[0][br][bc + 0] = f2tf(bv0.x); Bs[0][br][bc + 1] = f2tf(bv0.y);
        Bs[0][br][bc + 2] = f2tf(bv0.z); Bs[0][br][bc + 3] = f2tf(bv0.w);
        Bs[0][br][bc + 4] = f2tf(bv1.x); Bs[0][br][bc + 5] = f2tf(bv1.y);
        Bs[0][br][bc + 6] = f2tf(bv1.z); Bs[0][br][bc + 7] = f2tf(bv1.w);
    }
    __syncthreads();

    int cur = 0;
    for (int k0 = 0; k0 < K; k0 += 16) {
        int nk = k0 + 16;
        if (nk < K) {
            int m1 = m0 + ar, m2 = m0 + ar + 64;
            av0 = (m1 < M) ? *(const float4*)(X + (size_t)m1 * K + nk + ac) : z4;
            av1 = (m2 < M) ? *(const float4*)(X + (size_t)m2 * K + nk + ac) : z4;
            bv0 = *(const float4*)(W + (size_t)(nk + br) * HID + n0 + bc);
            bv1 = *(const float4*)(W + (size_t)(nk + br) * HID + n0 + bc + 4);
        }
#pragma unroll
        for (int ks = 0; ks < 2; ks++) {
            int kb = ks * 8;
            uint32_t af[2][4], bf[8][2];
#pragma unroll
            for (int mt = 0; mt < 2; mt++) {
                int m = wm * 32 + mt * 16 + g;
                af[mt][0] = As[cur][kb + t][m];
                af[mt][1] = As[cur][kb + t][m + 8];
                af[mt][2] = As[cur][kb + t + 4][m];
                af[mt][3] = As[cur][kb + t + 4][m + 8];
            }
#pragma unroll
            for (int j = 0; j < 8; j++) {
                int n = wn * 64 + j * 8 + g;
                bf[j][0] = Bs[cur][kb + t][n];
                bf[j][1] = Bs[cur][kb + t + 4][n];
            }
#pragma unroll
            for (int mt = 0; mt < 2; mt++)
#pragma unroll
                for (int j = 0; j < 8; j++)
                    mma_tf32(acc[mt][j], af[mt], bf[j]);
        }
        if (nk < K) {
            int nb = cur ^ 1;
            As[nb][ac + 0][ar] = f2tf(av0.x); As[nb][ac + 1][ar] = f2tf(av0.y);
            As[nb][ac + 2][ar] = f2tf(av0.z); As[nb][ac + 3][ar] = f2tf(av0.w);
            As[nb][ac + 0][ar + 64] = f2tf(av1.x); As[nb][ac + 1][ar + 64] = f2tf(av1.y);
            As[nb][ac + 2][ar + 64] = f2tf(av1.z); As[nb][ac + 3][ar + 64] = f2tf(av1.w);
            Bs[nb][br][bc + 0] = f2tf(bv0.x); Bs[nb][br][bc + 1] = f2tf(bv0.y);
            Bs[nb][br][bc + 2] = f2tf(bv0.z); Bs[nb][br][bc + 3] = f2tf(bv0.w);
            Bs[nb][br][bc + 4] = f2tf(bv1.x); Bs[nb][br][bc + 5] = f2tf(bv1.y);
            Bs[nb][br][bc + 6] = f2tf(bv1.z); Bs[nb][br][bc + 7] = f2tf(bv1.w);
            __syncthreads();
            cur = nb;
        }
    }

    // epilogue
#pragma unroll
    for (int mt = 0; mt < 2; mt++) {
#pragma unroll
        for (int rr = 0; rr < 2; rr++) {
            int gm = m0 + wm * 32 + mt * 16 + g + rr * 8;
            if (gm >= M) continue;
            int seq = 0, b = 0, s = 0;
            if (OUT_HEADMAJOR) {
                seq = gm / (BATCH * SA);
                int r = gm - seq * (BATCH * SA);
                b = r / SA;
                s = r - b * SA;
            }
#pragma unroll
            for (int j = 0; j < 8; j++) {
                int n = n0 + wn * 64 + j * 8 + t * 2;
                float2 o = make_float2(acc[mt][j][rr * 2] + bias[n],
                                       acc[mt][j][rr * 2 + 1] + bias[n + 1]);
                if (OUT_HEADMAJOR) {
                    int h = n >> 6, d = n & 63;
                    *(float2*)(Y + (size_t)seq * SEQSTR +
                               (((size_t)b * NH + h) * SA + s) * HD + d) = o;
                } else {
                    *(float2*)(Y + (size_t)gm * HID + n) = o;
                }
            }
        }
    }
}

// ---------------- TF32 flash attention, BQ=128, both dirs fused --------------
// q/k/v: [dir][B, NH, SA, HD]; out: [dir][B, SA, HID]
// Physics biases are per-row softmax-invariant constants -> dropped.
// blockIdx.z: bit0 = b, bit1 = dir. 256 threads = 8 warps, 16 q-rows/warp.
__global__ __launch_bounds__(256) void attn_tf32(
    const float* __restrict__ qall, const float* __restrict__ kall,
    const float* __restrict__ vall, float* __restrict__ attall)
{
    __shared__ uint32_t Ks[64][68];   // pad 68 (== 4 mod 32)
    __shared__ uint32_t Vs[64][72];   // pad 72 (== 8 mod 32)

    int qt = blockIdx.x, h = blockIdx.y;
    int b = blockIdx.z & 1, dir = blockIdx.z >> 1;
    const float* Q  = qall + (size_t)dir * SEQSTR;
    const float* Kx = kall + (size_t)(dir ^ 1) * SEQSTR;
    const float* V  = vall + (size_t)(dir ^ 1) * SEQSTR;
    float* attout   = attall + (size_t)dir * SEQSTR;

    int tid = threadIdx.x;
    int lane = tid & 31, warp = tid >> 5;
    int g = lane >> 2, t = lane & 3;
    const size_t hoff = ((size_t)b * NH + h) * (size_t)SA * HD;
    int q0 = qt * 128;

    // ---- stage Q (scaled by 1/8) in two 64-row passes through Ks ----
    uint32_t qf[8][4];
#pragma unroll
    for (int half = 0; half < 2; half++) {
        for (int i = tid; i < 64 * 16; i += 256) {
            int r = i >> 4, c = (i & 15) * 4;
            int gq = q0 + half * 64 + r;
            float4 v = make_float4(0.f, 0.f, 0.f, 0.f);
            if (gq < SA) v = *(const float4*)(Q + hoff + (size_t)gq * HD + c);
            Ks[r][c + 0] = f2tf(v.x * 0.125f); Ks[r][c + 1] = f2tf(v.y * 0.125f);
            Ks[r][c + 2] = f2tf(v.z * 0.125f); Ks[r][c + 3] = f2tf(v.w * 0.125f);
        }
        __syncthreads();
        if ((warp >> 2) == half) {
            int m = (warp & 3) * 16;
#pragma unroll
            for (int kc = 0; kc < 8; kc++) {
                qf[kc][0] = Ks[m + g][kc * 8 + t];
                qf[kc][1] = Ks[m + 8 + g][kc * 8 + t];
                qf[kc][2] = Ks[m + g][kc * 8 + t + 4];
                qf[kc][3] = Ks[m + 8 + g][kc * 8 + t + 4];
            }
        }
        __syncthreads();
    }

    float o[8][4];
#pragma unroll
    for (int nd = 0; nd < 8; nd++)
#pragma unroll
        for (int c = 0; c < 4; c++) o[nd][c] = 0.f;
    float mrow0 = -1e30f, mrow1 = -1e30f, lrow0 = 0.f, lrow1 = 0.f;

    for (int k0 = 0; k0 < SA; k0 += 64) {
        __syncthreads();
        for (int i = tid; i < 64 * 16; i += 256) {
            int r = i >> 4, c = (i & 15) * 4;
            int gk = k0 + r;
            float4 kv = make_float4(0.f, 0.f, 0.f, 0.f), vv = kv;
            if (gk < SA) {
                kv = *(const float4*)(Kx + hoff + (size_t)gk * HD + c);
                vv = *(const float4*)(V  + hoff + (size_t)gk * HD + c);
            }
            Ks[r][c + 0] = f2tf(kv.x); Ks[r][c + 1] = f2tf(kv.y);
            Ks[r][c + 2] = f2tf(kv.z); Ks[r][c + 3] = f2tf(kv.w);
            Vs[r][c + 0] = f2tf(vv.x); Vs[r][c + 1] = f2tf(vv.y);
            Vs[r][c + 2] = f2tf(vv.z); Vs[r][c + 3] = f2tf(vv.w);
        }
        __syncthreads();

        // ---- S = (Q/8) @ K^T ----
        float s[8][4];
#pragma unroll
        for (int j = 0; j < 8; j++)
#pragma unroll
            for (int c = 0; c < 4; c++) s[j][c] = 0.f;
#pragma unroll
        for (int j = 0; j < 8; j++) {
#pragma unroll
            for (int kc = 0; kc < 8; kc++) {
                uint32_t bf[2];
                bf[0] = Ks[j * 8 + g][kc * 8 + t];
                bf[1] = Ks[j * 8 + g][kc * 8 + t + 4];
                mma_tf32(s[j], qf[kc], bf);
            }
        }

        // ---- mask invalid keys ----
        int kvalid = SA - k0;
        if (kvalid < 64) {
#pragma unroll
            for (int j = 0; j < 8; j++) {
                int c0 = j * 8 + t * 2, c1 = c0 + 1;
                if (c0 >= kvalid) { s[j][0] = -1e30f; s[j][2] = -1e30f; }
                if (c1 >= kvalid) { s[j][1] = -1e30f; s[j][3] = -1e30f; }
            }
        }

        // ---- online softmax (rows g, g+8 spread over 4 lanes) ----
        float tm0 = -1e30f, tm1 = -1e30f;
#pragma unroll
        for (int j = 0; j < 8; j++) {
            tm0 = fmaxf(tm0, fmaxf(s[j][0], s[j][1]));
            tm1 = fmaxf(tm1, fmaxf(s[j][2], s[j][3]));
        }
        tm0 = fmaxf(tm0, __shfl_xor_sync(0xffffffffu, tm0, 1));
        tm0 = fmaxf(tm0, __shfl_xor_sync(0xffffffffu, tm0, 2));
        tm1 = fmaxf(tm1, __shfl_xor_sync(0xffffffffu, tm1, 1));
        tm1 = fmaxf(tm1, __shfl_xor_sync(0xffffffffu, tm1, 2));
        float nm0 = fmaxf(mrow0, tm0), nm1 = fmaxf(mrow1, tm1);
        float corr0 = __expf(mrow0 - nm0), corr1 = __expf(mrow1 - nm1);
        float sum0 = 0.f, sum1 = 0.f;
#pragma unroll
        for (int j = 0; j < 8; j++) {
            s[j][0] = __expf(s[j][0] - nm0);
            s[j][1] = __expf(s[j][1] - nm0);
            s[j][2] = __expf(s[j][2] - nm1);
            s[j][3] = __expf(s[j][3] - nm1);
            sum0 += s[j][0] + s[j][1];
            sum1 += s[j][2] + s[j][3];
        }
        sum0 += __shfl_xor_sync(0xffffffffu, sum0, 1);
        sum0 += __shfl_xor_sync(0xffffffffu, sum0, 2);
        sum1 += __shfl_xor_sync(0xffffffffu, sum1, 1);
        sum1 += __shfl_xor_sync(0xffffffffu, sum1, 2);
        lrow0 = lrow0 * corr0 + sum0;  mrow0 = nm0;
        lrow1 = lrow1 * corr1 + sum1;  mrow1 = nm1;
#pragma unroll
        for (int nd = 0; nd < 8; nd++) {
            o[nd][0] *= corr0; o[nd][1] *= corr0;
            o[nd][2] *= corr1; o[nd][3] *= corr1;
        }

        // ---- O += P @ V (P -> A-fragments via shuffles) ----
        int s0l = (lane & 28) + (t >> 1);
#pragma unroll
        for (int j = 0; j < 8; j++) {
            float e0 = __shfl_sync(0xffffffffu, s[j][0], s0l);
            float e1 = __shfl_sync(0xffffffffu, s[j][1], s0l);
            float f0 = __shfl_sync(0xffffffffu, s[j][2], s0l);
            float f1 = __shfl_sync(0xffffffffu, s[j][3], s0l);
            float e2 = __shfl_sync(0xffffffffu, s[j][0], s0l + 2);
            float e3 = __shfl_sync(0xffffffffu, s[j][1], s0l + 2);
            float f2 = __shfl_sync(0xffffffffu, s[j][2], s0l + 2);
            float f3 = __shfl_sync(0xffffffffu, s[j][3], s0l + 2);
            uint32_t af[4];
            af[0] = f2tf((t & 1) ? e1 : e0);
            af[1] = f2tf((t & 1) ? f1 : f0);
            af[2] = f2tf((t & 1) ? e3 : e2);
            af[3] = f2tf((t & 1) ? f3 : f2);
#pragma unroll
            for (int nd = 0; nd < 8; nd++) {
                uint32_t bf[2];
                bf[0] = Vs[j * 8 + t][nd * 8 + g];
                bf[1] = Vs[j * 8 + t + 4][nd * 8 + g];
                mma_tf32(o[nd], af, bf);
            }
        }
    }

    // ---- write attended rows ----
    float inv0 = 1.0f / lrow0, inv1 = 1.0f / lrow1;
    int row0 = q0 + warp * 16 + g, row1 = row0 + 8;
    int cb = h * HD;
#pragma unroll
    for (int nd = 0; nd < 8; nd++) {
        int col = cb + nd * 8 + t * 2;
        if (row0 < SA) {
            float2 v = make_float2(o[nd][0] * inv0, o[nd][1] * inv0);
            *(float2*)(attout + ((size_t)b * SA + row0) * HID + col) = v;
        }
        if (row1 < SA) {
            float2 v = make_float2(o[nd][2] * inv1, o[nd][3] * inv1);
            *(float2*)(attout + ((size_t)b * SA + row1) * HID + col) = v;
        }
    }
}

// ---------------- residual + LayerNorm epilogue ------------------------------
__global__ __launch_bounds__(256) void ln_kernel(
    const float* __restrict__ aug, const float* __restrict__ proj,
    const float* __restrict__ gamma, const float* __restrict__ beta,
    float* __restrict__ out)
{
    int s = blockIdx.x, b = blockIdx.y, seq = blockIdx.z;
    int tid = threadIdx.x;
    size_t roff = (((size_t)seq * BATCH + b) * SA + s) * HID;
    int j = tid * 4;

    float4 a = *(const float4*)(aug + roff + j);
    float4 p = *(const float4*)(proj + roff + j);
    float4 x = make_float4(a.x + p.x, a.y + p.y, a.z + p.z, a.w + p.w);

    __shared__ float wsum[8];
    float lsum = x.x + x.y + x.z + x.w;
#pragma unroll
    for (int m = 16; m >= 1; m >>= 1) lsum += __shfl_xor_sync(0xffffffffu, lsum, m);
    if ((tid & 31) == 0) wsum[tid >> 5] = lsum;
    __syncthreads();
    float tot = 0.f;
#pragma unroll
    for (int w = 0; w < 8; w++) tot += wsum[w];
    float mean = tot * (1.0f / HID);

    float dx = x.x - mean, dy = x.y - mean, dz = x.z - mean, dw = x.w - mean;
    float lvar = dx * dx + dy * dy + dz * dz + dw * dw;
#pragma unroll
    for (int m = 16; m >= 1; m >>= 1) lvar += __shfl_xor_sync(0xffffffffu, lvar, m);
    __syncthreads();
    if ((tid & 31) == 0) wsum[tid >> 5] = lvar;
    __syncthreads();
    float tot2 = 0.f;
#pragma unroll
    for (int w = 0; w < 8; w++) tot2 += wsum[w];
    float rstd = rsqrtf(tot2 * (1.0f / HID) + 1e-5f);

    float4 g = *(const float4*)(gamma + j);
    float4 be = *(const float4*)(beta + j);
    float4 oo = make_float4(dx * rstd * g.x + be.x, dy * rstd * g.y + be.y,
                            dz * rstd * g.z + be.z, dw * rstd * g.w + be.w);
    size_t oidx = (size_t)seq * (2ull * SEQ * HID) + ((size_t)b * SEQ + s) * HID + j;
    *(float4*)(out + oidx) = oo;
}

// ---------------- launch ------------------------------------------------------
extern "C" void kernel_launch(void* const* d_in, const int* in_sizes, int n_in,
                              void* d_out, int out_size)
{
    const float* cnn = (const float*)d_in[0];
    const float* llm = (const float*)d_in[1];
    const float* Wq  = (const float*)d_in[2];  const float* bq = (const float*)d_in[3];
    const float* Wk  = (const float*)d_in[4];  const float* bk = (const float*)d_in[5];
    const float* Wv  = (const float*)d_in[6];  const float* bv = (const float*)d_in[7];
    const float* Wo  = (const float*)d_in[8];  const float* bo = (const float*)d_in[9];
    const float* ee  = (const float*)d_in[10];
    const float* me  = (const float*)d_in[11];
    const float* pe  = (const float*)d_in[12];
    const float* gamma = (const float*)d_in[13];
    const float* beta  = (const float*)d_in[14];

    float *aug, *q, *k, *v, *att, *proj;
    cudaGetSymbolAddress((void**)&aug,  g_aug);
    cudaGetSymbolAddress((void**)&q,    g_q);
    cudaGetSymbolAddress((void**)&k,    g_k);
    cudaGetSymbolAddress((void**)&v,    g_v);
    cudaGetSymbolAddress((void**)&att,  g_att);
    cudaGetSymbolAddress((void**)&proj, g_proj);

    build_aug_kernel<<<dim3(SA, BATCH, 2), 256>>>(cnn, llm, ee, me, pe, aug);

    const int M = MROWS;                              // 8204
    dim3 gqkv((M + 127) / 128, HID / 128, 3);         // (65, 8, 3)
    sgemm_tf32<1><<<gqkv, 256>>>(aug, Wq, Wk, Wv, bq, bk, bv, q, k, v, M);

    dim3 ga((SA + 127) / 128, NH, 4);                 // (17, 16, 4)
    attn_tf32<<<ga, 256>>>(q, k, v, att);

    dim3 go((M + 127) / 128, HID / 128, 1);           // (65, 8)
    sgemm_tf32<0><<<go, 256>>>(att, Wo, Wo, Wo, bo, bo, bo, proj, proj, proj, M);

    ln_kernel<<<dim3(SEQ, BATCH, 2), 256>>>(aug, proj, gamma, beta, (float*)d_out);
}